// round 3
// baseline (speedup 1.0000x reference)
#include <cuda_runtime.h>
#include <cuda_bf16.h>

// ---------------------------------------------------------------------------
// Compile-time D4 codebook (values stored as integers = 2*g, in {±1,±3,±5}),
// replicated exactly from the reference _code8_to_d4 builder.
// Integer constexpr only -> safe to use in device code without relaxed-constexpr.
// ---------------------------------------------------------------------------
__host__ __device__ constexpr int cw2(int i8, int j) {
    int v[4] = {0, 0, 0, 0};
    int b = i8 & 31;
    if (b < 16) {
        if (b < 8) {
            if (b < 2) {
                if (b < 1) { v[0] = 1; v[1] = 1; v[2] = 1; v[3] = 1; }
                else       { v[0] = 3; v[1] = 3; v[2] = 3; v[3] = 3; }
            } else {
                int ibx = b >> 1;
                if (b & 1) { v[0] = 1; v[1] = 1; v[2] = 1; v[3] = 1; v[0] = 3; v[ibx] = 3; }
                else       { v[0] = 3; v[1] = 3; v[2] = 3; v[3] = 3; v[0] = 1; v[ibx] = 1; }
            }
        } else {
            int ibx = b & 3;
            if (b < 12) { v[0] = 1; v[1] = 1; v[2] = 1; v[3] = 1; v[ibx] = 3; }
            else        { v[0] = 3; v[1] = 3; v[2] = 3; v[3] = 3; v[ibx] = 1; }
        }
    } else if (b < 20) {
        int ibx = b & 3;
        v[0] = 1; v[1] = 1; v[2] = 1; v[3] = 1; v[ibx] = 5;
    } else {
        int ibx = b - 20;
        int ib4 = ibx & 3;
        int ib3 = ibx >> 2;
        v[0] = 1; v[1] = 1; v[2] = 1; v[3] = 1;
        v[ib4] = 3;
        if (ib3 >= ib4) ib3 += 1;
        v[ib3] = 5;
    }
    // _code3_signs
    if (i8 & 32) v[2] = -v[2];
    if (i8 & 64) v[1] = -v[1];
    int s = v[0] + v[1] + v[2] + v[3];   // = 2 * sum(x), always even
    int sumx = s / 2;                    // exact (s even)
    if (sumx & 1) v[3] = -v[3];          // parity fix (works for negatives: -3 & 1 == 1)
    if (i8 & 128) { v[0] = -v[0]; v[1] = -v[1]; v[2] = -v[2]; v[3] = -v[3]; }
    return v[j];
}

__host__ __device__ constexpr int cnorm(int i8) {
    int s = 0;
    for (int j = 0; j < 4; j++) { int v = cw2(i8, j); s += v * v; }
    return s / 4;   // |g|^2 in {1,3,5,7,9}, exact
}

// ---------------------------------------------------------------------------
// Fully unrolled candidate loop over the 128 +/- pairs, all codebook constants
// folded into FFMA immediates (rt_SMSP = 1 imm form).
// score(k)       = 2*d - n
// score(k + 128) = -2*d - n        (grid[k+128] == -grid[k] exactly)
// max of pair    = 2*|d| - n ; sign(d) < 0 -> winner index is k + 128.
// d is computed with the ascending fma chain to mirror the reference einsum.
// ---------------------------------------------------------------------------
template <int K, int END>
struct Loop {
    static __device__ __forceinline__ void run(float x0, float x1, float x2, float x3,
                                               float& best, int& bk, float& bd) {
        constexpr float g0 = (float)cw2(K, 0) * 0.5f;
        constexpr float g1 = (float)cw2(K, 1) * 0.5f;
        constexpr float g2 = (float)cw2(K, 2) * 0.5f;
        constexpr float g3 = (float)cw2(K, 3) * 0.5f;
        constexpr float nn = (float)(-cnorm(K));
        float d = x0 * g0;
        d = fmaf(x1, g1, d);
        d = fmaf(x2, g2, d);
        d = fmaf(x3, g3, d);
        float s = fmaf(fabsf(d), 2.0f, nn);
        if (s > best) { best = s; bk = K; bd = d; }
        Loop<K + 1, END>::run(x0, x1, x2, x3, best, bk, bd);
    }
};
template <int END>
struct Loop<END, END> {
    static __device__ __forceinline__ void run(float, float, float, float,
                                               float&, int&, float&) {}
};

template <bool IDX_FLOAT>
__global__ __launch_bounds__(256) void d4_kernel(const float4* __restrict__ X,
                                                 const float4* __restrict__ grid,
                                                 float* __restrict__ out,
                                                 int n) {
    int i = blockIdx.x * blockDim.x + threadIdx.x;
    if (i >= n) return;

    float4 x = X[i];

    float best = -3.0e38f;
    int bk = 0;
    float bd = 0.0f;
    Loop<0, 128>::run(x.x, x.y, x.z, x.w, best, bk, bd);

    int kk = bk | ((bd < 0.0f) ? 128 : 0);

    // winner codeword values, read from the harness-provided grid -> bit-exact
    reinterpret_cast<float4*>(out)[i] = grid[kk];

    if (IDX_FLOAT) {
        out[(long long)4 * n + i] = (float)kk;
    } else {
        reinterpret_cast<unsigned char*>(out)[(long long)16 * n + i] = (unsigned char)kk;
    }
}

extern "C" void kernel_launch(void* const* d_in, const int* in_sizes, int n_in,
                              void* d_out, int out_size) {
    const float4* X    = (const float4*)d_in[0];
    const float4* grid = (const float4*)d_in[1];
    // d_in[2] = grid_norm, unneeded: norms are the exact constants {1,3,5,7,9}

    int n = in_sizes[0] / 4;
    int blocks = (n + 255) / 256;

    long long out5 = 5LL * n;   // grid-values (4n floats) + idx as float (n floats)
    if ((long long)out_size >= out5) {
        d4_kernel<true><<<blocks, 256>>>(X, grid, (float*)d_out, n);
    } else {
        // idx packed as raw uint8 bytes after the 16n bytes of float values
        d4_kernel<false><<<blocks, 256>>>(X, grid, (float*)d_out, n);
    }
}

// round 4
// speedup vs baseline: 1.1306x; 1.1306x over previous
#include <cuda_runtime.h>
#include <cuda_bf16.h>

// ---------------------------------------------------------------------------
// Compile-time D4 codebook (values stored as integers = 2*g, in {±1,±3,±5}),
// replicated exactly from the reference _code8_to_d4 builder.
// ---------------------------------------------------------------------------
__host__ __device__ constexpr int cw2(int i8, int j) {
    int v[4] = {0, 0, 0, 0};
    int b = i8 & 31;
    if (b < 16) {
        if (b < 8) {
            if (b < 2) {
                if (b < 1) { v[0] = 1; v[1] = 1; v[2] = 1; v[3] = 1; }
                else       { v[0] = 3; v[1] = 3; v[2] = 3; v[3] = 3; }
            } else {
                int ibx = b >> 1;
                if (b & 1) { v[0] = 1; v[1] = 1; v[2] = 1; v[3] = 1; v[0] = 3; v[ibx] = 3; }
                else       { v[0] = 3; v[1] = 3; v[2] = 3; v[3] = 3; v[0] = 1; v[ibx] = 1; }
            }
        } else {
            int ibx = b & 3;
            if (b < 12) { v[0] = 1; v[1] = 1; v[2] = 1; v[3] = 1; v[ibx] = 3; }
            else        { v[0] = 3; v[1] = 3; v[2] = 3; v[3] = 3; v[ibx] = 1; }
        }
    } else if (b < 20) {
        int ibx = b & 3;
        v[0] = 1; v[1] = 1; v[2] = 1; v[3] = 1; v[ibx] = 5;
    } else {
        int ibx = b - 20;
        int ib4 = ibx & 3;
        int ib3 = ibx >> 2;
        v[0] = 1; v[1] = 1; v[2] = 1; v[3] = 1;
        v[ib4] = 3;
        if (ib3 >= ib4) ib3 += 1;
        v[ib3] = 5;
    }
    if (i8 & 32) v[2] = -v[2];
    if (i8 & 64) v[1] = -v[1];
    int s = v[0] + v[1] + v[2] + v[3];   // 2 * sum(x), always even
    int sumx = s / 2;
    if (sumx & 1) v[3] = -v[3];
    if (i8 & 128) { v[0] = -v[0]; v[1] = -v[1]; v[2] = -v[2]; v[3] = -v[3]; }
    return v[j];
}

__host__ __device__ constexpr int cnorm(int i8) {
    int s = 0;
    for (int j = 0; j < 4; j++) { int v = cw2(i8, j); s += v * v; }
    return s / 4;   // |g|^2 in {1,3,5,7,9}, exact
}

// ---- packed-byte table of 2*g for recovery pass (constant, compile-time) ----
struct PK { unsigned v[128]; };
__host__ __device__ constexpr PK mkpk() {
    PK t{};
    for (int k = 0; k < 128; k++) {
        unsigned u = 0;
        for (int j = 0; j < 4; j++) {
            int c = cw2(k, j);
            u |= ((unsigned)(c & 0xFF)) << (8 * j);
        }
        t.v[k] = u;
    }
    return t;
}
__constant__ PK g_pk = mkpk();

// ---- 12-entry packed f32x2 constant vocabulary -----------------------------
// magnitudes m2 in {1,3,5} (units of 0.5), sign combos (lo,hi): ++, +-, -+, --
__host__ __device__ constexpr unsigned fbits(int c2) {
    int a = c2 < 0 ? -c2 : c2;
    unsigned base = (a == 1) ? 0x3F000000u : (a == 3) ? 0x3FC00000u : 0x40200000u;
    return base | (c2 < 0 ? 0x80000000u : 0u);
}
__host__ __device__ constexpr unsigned long long packc(int lo2, int hi2) {
    return ((unsigned long long)fbits(hi2) << 32) | (unsigned long long)fbits(lo2);
}
// compile-time vocabulary index for pattern P, coord j, variant-pair (va, vb)
__host__ __device__ constexpr int ci(int P, int j, int va, int vb) {
    int a = cw2(P | (va << 5), j);
    int b = cw2(P | (vb << 5), j);
    int m = a < 0 ? -a : a;          // magnitudes equal across variants
    return ((m - 1) / 2) * 4 + (a < 0 ? 2 : 0) + (b < 0 ? 1 : 0);
}

#define MUL2(d, a, b)    asm("mul.rn.f32x2 %0, %1, %2;"     : "=l"(d) : "l"(a), "l"(b))
#define FMA2(d, a, b, c) asm("fma.rn.f32x2 %0, %1, %2, %3;" : "=l"(d) : "l"(a), "l"(b), "l"(c))
#define PACK2(o, lo, hi) asm("mov.b64 %0, {%1, %2};" : "=l"(o) : "f"(lo), "f"(hi))
#define UNPK2(lo, hi, i) asm("mov.b64 {%0, %1}, %2;" : "=f"(lo), "=f"(hi) : "l"(i))

// ---------------------------------------------------------------------------
// One magnitude pattern = 4 candidates (sign variants v = 0..3, k = P | v<<5).
// Lanes: pair A = (v0, v1), pair B = (v2, v3). Each lane computes the exact
// reference fma chain. Per-pattern score uses the shared norm:
//   s = 2 * max|d| - n   (exact: *2 exact, max exact, same final fma as ref)
// ---------------------------------------------------------------------------
template <int P>
struct Pat {
    static __device__ __forceinline__ void run(const unsigned long long (&C)[12],
                                               const unsigned long long (&xx)[4],
                                               float& best, int& bp) {
        unsigned long long dA, dB;
        MUL2(dA, xx[0], C[ci(P, 0, 0, 1)]);
        FMA2(dA, xx[1], C[ci(P, 1, 0, 1)], dA);
        FMA2(dA, xx[2], C[ci(P, 2, 0, 1)], dA);
        FMA2(dA, xx[3], C[ci(P, 3, 0, 1)], dA);
        MUL2(dB, xx[0], C[ci(P, 0, 2, 3)]);
        FMA2(dB, xx[1], C[ci(P, 1, 2, 3)], dB);
        FMA2(dB, xx[2], C[ci(P, 2, 2, 3)], dB);
        FMA2(dB, xx[3], C[ci(P, 3, 2, 3)], dB);
        float a0, a1, b0, b1;
        UNPK2(a0, a1, dA);
        UNPK2(b0, b1, dB);
        float gm = fmaxf(fmaxf(fabsf(a0), fabsf(a1)), fmaxf(fabsf(b0), fabsf(b1)));
        float s = fmaf(gm, 2.0f, (float)(-cnorm(P)));
        if (P == 0) {
            best = s; bp = 0;
        } else {
            bool w = s > best;             // strict >: lower pattern wins ties
            best = fmaxf(best, s);
            bp = w ? P : bp;
        }
        Pat<P + 1>::run(C, xx, best, bp);
    }
};
template <>
struct Pat<32> {
    static __device__ __forceinline__ void run(const unsigned long long (&)[12],
                                               const unsigned long long (&)[4],
                                               float&, int&) {}
};

template <bool IDX_FLOAT>
__global__ __launch_bounds__(256, 4) void d4_kernel(const float4* __restrict__ X,
                                                    const float4* __restrict__ grid,
                                                    float* __restrict__ out,
                                                    int n) {
    int i = blockIdx.x * blockDim.x + threadIdx.x;
    if (i >= n) return;

    float4 x = X[i];

    // packed operands: (x_j, x_j)
    unsigned long long xx[4];
    PACK2(xx[0], x.x, x.x);
    PACK2(xx[1], x.y, x.y);
    PACK2(xx[2], x.z, x.z);
    PACK2(xx[3], x.w, x.w);

    // 12 packed multiplier constants (uniform across warp)
    unsigned long long C[12];
#pragma unroll
    for (int mi = 0; mi < 3; mi++) {
        const int m2 = 2 * mi + 1;
        C[mi * 4 + 0] = packc( m2,  m2);
        C[mi * 4 + 1] = packc( m2, -m2);
        C[mi * 4 + 2] = packc(-m2,  m2);
        C[mi * 4 + 3] = packc(-m2, -m2);
    }

    float best;
    int bp;
    Pat<0>::run(C, xx, best, bp);

    // ---- recovery: re-derive exact winning candidate within pattern bp ----
    // Recompute the 4 signed dots with the identical chain (bitwise equal to
    // the FFMA2 lanes), rebuild the pattern max, scan variants ascending.
    float dv[4];
#pragma unroll
    for (int v = 0; v < 4; v++) {
        int k = bp + (v << 5);
        unsigned u = g_pk.v[k];
        float g0 = (float)(signed char)(u)        * 0.5f;
        float g1 = (float)(signed char)(u >> 8)   * 0.5f;
        float g2 = (float)(signed char)(u >> 16)  * 0.5f;
        float g3 = (float)(signed char)(u >> 24)  * 0.5f;
        float d = x.x * g0;
        d = fmaf(x.y, g1, d);
        d = fmaf(x.z, g2, d);
        d = fmaf(x.w, g3, d);
        dv[v] = d;
    }
    float gmr = fmaxf(fmaxf(fabsf(dv[0]), fabsf(dv[1])),
                      fmaxf(fabsf(dv[2]), fabsf(dv[3])));
    int kk = 0;
    bool found = false;
#pragma unroll
    for (int v = 0; v < 4; v++) {
        bool hit = (!found) && (fabsf(dv[v]) == gmr);
        if (hit) kk = (bp + (v << 5)) | ((dv[v] < 0.0f) ? 128 : 0);
        found = found || hit;
    }
    if (!found) kk = bp | ((dv[0] < 0.0f) ? 128 : 0);  // unreachable safety net

    // winner codeword values read from harness grid -> bit-exact
    reinterpret_cast<float4*>(out)[i] = grid[kk];

    if (IDX_FLOAT) {
        out[(long long)4 * n + i] = (float)kk;
    } else {
        reinterpret_cast<unsigned char*>(out)[(long long)16 * n + i] = (unsigned char)kk;
    }
}

extern "C" void kernel_launch(void* const* d_in, const int* in_sizes, int n_in,
                              void* d_out, int out_size) {
    const float4* X    = (const float4*)d_in[0];
    const float4* grid = (const float4*)d_in[1];
    // d_in[2] = grid_norm, unneeded: norms are the exact constants {1,3,5,7,9}

    int n = in_sizes[0] / 4;
    int blocks = (n + 255) / 256;

    long long out5 = 5LL * n;
    if ((long long)out_size >= out5) {
        d4_kernel<true><<<blocks, 256>>>(X, grid, (float*)d_out, n);
    } else {
        d4_kernel<false><<<blocks, 256>>>(X, grid, (float*)d_out, n);
    }
}

// round 9
// speedup vs baseline: 1.3253x; 1.1722x over previous
#include <cuda_runtime.h>
#include <cuda_bf16.h>

// ---------------------------------------------------------------------------
// Compile-time D4 codebook (values stored as integers = 2*g, in {±1,±3,±5}),
// replicated exactly from the reference _code8_to_d4 builder.
// ---------------------------------------------------------------------------
__host__ __device__ constexpr int cw2(int i8, int j) {
    int v[4] = {0, 0, 0, 0};
    int b = i8 & 31;
    if (b < 16) {
        if (b < 8) {
            if (b < 2) {
                if (b < 1) { v[0] = 1; v[1] = 1; v[2] = 1; v[3] = 1; }
                else       { v[0] = 3; v[1] = 3; v[2] = 3; v[3] = 3; }
            } else {
                int ibx = b >> 1;
                if (b & 1) { v[0] = 1; v[1] = 1; v[2] = 1; v[3] = 1; v[0] = 3; v[ibx] = 3; }
                else       { v[0] = 3; v[1] = 3; v[2] = 3; v[3] = 3; v[0] = 1; v[ibx] = 1; }
            }
        } else {
            int ibx = b & 3;
            if (b < 12) { v[0] = 1; v[1] = 1; v[2] = 1; v[3] = 1; v[ibx] = 3; }
            else        { v[0] = 3; v[1] = 3; v[2] = 3; v[3] = 3; v[ibx] = 1; }
        }
    } else if (b < 20) {
        int ibx = b & 3;
        v[0] = 1; v[1] = 1; v[2] = 1; v[3] = 1; v[ibx] = 5;
    } else {
        int ibx = b - 20;
        int ib4 = ibx & 3;
        int ib3 = ibx >> 2;
        v[0] = 1; v[1] = 1; v[2] = 1; v[3] = 1;
        v[ib4] = 3;
        if (ib3 >= ib4) ib3 += 1;
        v[ib3] = 5;
    }
    if (i8 & 32) v[2] = -v[2];
    if (i8 & 64) v[1] = -v[1];
    int s = v[0] + v[1] + v[2] + v[3];   // 2 * sum(x), always even
    int sumx = s / 2;
    if (sumx & 1) v[3] = -v[3];
    if (i8 & 128) { v[0] = -v[0]; v[1] = -v[1]; v[2] = -v[2]; v[3] = -v[3]; }
    return v[j];
}

__host__ __device__ constexpr int cnorm(int i8) {
    int s = 0;
    for (int j = 0; j < 4; j++) { int v = cw2(i8, j); s += v * v; }
    return s / 4;   // |g|^2 in {1,3,5,7,9}, exact
}

// magnitude index (0=0.5, 1=1.5, 2=2.5) of pattern P, coord j
__host__ __device__ constexpr int mag(int P, int j) {
    int c = cw2(P, j);
    int a = c < 0 ? -c : c;
    return (a - 1) / 2;
}
// parity-class bit of pattern: parity of count of 1.5-magnitude coordinates.
// A sign assignment s is representable iff (#neg(s) mod 2) == bsel(P).
__host__ __device__ constexpr int bsel(int P) {
    int s = 0;
    for (int j = 0; j < 4; j++) s += 2 * mag(P, j) + 1;
    return (s % 4) / 2;
}

// ---- codeword float table for exact recovery / slow path -------------------
struct F4 { float x, y, z, w; };
struct G4 { F4 v[128]; };
__host__ __device__ constexpr G4 mkf4() {
    G4 t{};
    for (int k = 0; k < 128; k++) {
        t.v[k].x = (float)cw2(k, 0) * 0.5f;
        t.v[k].y = (float)cw2(k, 1) * 0.5f;
        t.v[k].z = (float)cw2(k, 2) * 0.5f;
        t.v[k].w = (float)cw2(k, 3) * 0.5f;
    }
    return t;
}
__device__ __align__(16) const G4 g_f4 = mkf4();

struct NN { float v[32]; };
__host__ __device__ constexpr NN mknn() {
    NN t{};
    for (int P = 0; P < 32; P++) t.v[P] = -(float)cnorm(P);
    return t;
}
__device__ const NN g_nn = mknn();

// ---------------------------------------------------------------------------
// Phase 1: per magnitude pattern (8 even-parity sign candidates each),
//   halfscore = (sum4 - wrong*2*min4) + (16 - n/2)    [positive, monotone]
//   packed    = (bits(halfscore) & ~31) | P           [argmax via unsigned max]
// sum4/min4 trees share pair subexpressions across patterns (ptxas CSE).
// ---------------------------------------------------------------------------
template <int P>
struct Pat1 {
    static __device__ __forceinline__ void run(const float (&A)[3][4],
                                               float npm0, float npm1,
                                               unsigned& best, unsigned& second) {
        constexpr int i0 = mag(P, 0), i1 = mag(P, 1), i2 = mag(P, 2), i3 = mag(P, 3);
        constexpr float cofs = 16.0f - 0.5f * (float)cnorm(P);
        float s01 = A[i0][0] + A[i1][1];
        float s23 = A[i2][2] + A[i3][3];
        float m01 = fminf(A[i0][0], A[i1][1]);
        float m23 = fminf(A[i2][2], A[i3][3]);
        float sum = s01 + s23;
        float mn  = fminf(m01, m23);
        float adj = fmaf(bsel(P) ? npm1 : npm0, mn, sum);
        float sh  = adj + cofs;
        unsigned u = (__float_as_uint(sh) & 0xFFFFFFE0u) | (unsigned)P;
        unsigned t = umin(u, best);
        second = umax(second, t);
        best   = umax(best, u);
        Pat1<P + 1>::run(A, npm0, npm1, best, second);
    }
};
template <>
struct Pat1<32> {
    static __device__ __forceinline__ void run(const float (&)[3][4], float, float,
                                               unsigned&, unsigned&) {}
};

template <bool IDX_FLOAT>
__global__ __launch_bounds__(256, 5) void d4_kernel(const float4* __restrict__ X,
                                                    const float4* __restrict__ grid,
                                                    float* __restrict__ out,
                                                    int n) {
    int i = blockIdx.x * blockDim.x + threadIdx.x;
    if (i >= n) return;

    float4 x = X[i];

    // 12 shared magnitude products m*|x_j| (abs folds into FMUL modifier)
    float A[3][4];
    A[0][0] = 0.5f * fabsf(x.x); A[1][0] = 1.5f * fabsf(x.x); A[2][0] = 2.5f * fabsf(x.x);
    A[0][1] = 0.5f * fabsf(x.y); A[1][1] = 1.5f * fabsf(x.y); A[2][1] = 2.5f * fabsf(x.y);
    A[0][2] = 0.5f * fabsf(x.z); A[1][2] = 1.5f * fabsf(x.z); A[2][2] = 2.5f * fabsf(x.z);
    A[0][3] = 0.5f * fabsf(x.w); A[1][3] = 1.5f * fabsf(x.w); A[2][3] = 2.5f * fabsf(x.w);

    // parity of negative-coordinate count
    unsigned sb = (__float_as_uint(x.x) ^ __float_as_uint(x.y)) ^
                  (__float_as_uint(x.z) ^ __float_as_uint(x.w));
    int parbit = (int)(sb >> 31);
    // flip penalty is 2 * min product: npm in {0, -2}
    // B=0 patterns wrong iff parbit=1; B=1 patterns wrong iff parbit=0
    float npm0 = parbit ? -2.0f : 0.0f;
    float npm1 = parbit ? 0.0f : -2.0f;

    unsigned best = 0u, second = 0u;
    Pat1<0>::run(A, npm0, npm1, best, second);

    int bp = (int)(best & 31u);

    // ---- δ-guard: if runner-up within 128 ULP-ints, resolve exactly --------
    if (best - second < 128u) {
        const float4* gt = reinterpret_cast<const float4*>(g_f4.v);
        float bs = -3.0e38f;
        int bpp = 0;
#pragma unroll 1
        for (int P = 0; P < 32; P++) {
            float gm = 0.0f;
#pragma unroll
            for (int v = 0; v < 4; v++) {
                float4 g = gt[P + (v << 5)];
                float d = x.x * g.x;
                d = fmaf(x.y, g.y, d);
                d = fmaf(x.z, g.z, d);
                d = fmaf(x.w, g.w, d);
                gm = fmaxf(gm, fabsf(d));
            }
            float s = fmaf(gm, 2.0f, g_nn.v[P]);
            if (s > bs) { bs = s; bpp = P; }   // strict >: lowest pattern wins ties
        }
        bp = bpp;
    }

    // ---- recovery: exact reference-chain dots for the 4 variants of bp -----
    const float4* gt = reinterpret_cast<const float4*>(g_f4.v);
    float dv[4];
#pragma unroll
    for (int v = 0; v < 4; v++) {
        float4 g = gt[bp + (v << 5)];
        float d = x.x * g.x;
        d = fmaf(x.y, g.y, d);
        d = fmaf(x.z, g.z, d);
        d = fmaf(x.w, g.w, d);
        dv[v] = d;
    }
    float gmr = fmaxf(fmaxf(fabsf(dv[0]), fabsf(dv[1])),
                      fmaxf(fabsf(dv[2]), fabsf(dv[3])));
    int kk = bp;
    bool found = false;
#pragma unroll
    for (int v = 0; v < 4; v++) {
        bool hit = (!found) && (fabsf(dv[v]) == gmr);
        if (hit) kk = (bp + (v << 5)) | ((dv[v] < 0.0f) ? 128 : 0);
        found = found || hit;
    }

    // winner codeword values read from harness grid -> bit-exact
    reinterpret_cast<float4*>(out)[i] = grid[kk];

    if (IDX_FLOAT) {
        out[(long long)4 * n + i] = (float)kk;
    } else {
        reinterpret_cast<unsigned char*>(out)[(long long)16 * n + i] = (unsigned char)kk;
    }
}

extern "C" void kernel_launch(void* const* d_in, const int* in_sizes, int n_in,
                              void* d_out, int out_size) {
    const float4* X    = (const float4*)d_in[0];
    const float4* grid = (const float4*)d_in[1];
    // d_in[2] = grid_norm, unneeded: norms are the exact constants {1,3,5,7,9}

    int n = in_sizes[0] / 4;
    int blocks = (n + 255) / 256;

    long long out5 = 5LL * n;
    if ((long long)out_size >= out5) {
        d4_kernel<true><<<blocks, 256>>>(X, grid, (float*)d_out, n);
    } else {
        d4_kernel<false><<<blocks, 256>>>(X, grid, (float*)d_out, n);
    }
}